// round 3
// baseline (speedup 1.0000x reference)
#include <cuda_runtime.h>
#include <cstddef>

#define B 8
#define C 512
#define HW 4096
#define M_TOT (B*HW)          // 32768
#define NG 32
#define CPG (C/NG)            // 16
#define GRP_ELEMS (CPG*HW)    // 65536
#define NHEAD 8
#define HD 64
#define EPS_GN 1e-6f
#define SCALE_ATT 8.0f        // sqrt(64), reference MULTIPLIES

// ---------------- scratch (static device allocations, allowed) ----------------
__device__ float g_xn [B*C*HW];        // normalized x, (b,c,p) layout
__device__ float g_q  [(size_t)M_TOT*C];
__device__ float g_k  [(size_t)M_TOT*C];
__device__ float g_v  [(size_t)M_TOT*C];
__device__ float g_att[(size_t)B*NHEAD*NHEAD*HW]; // dots then att, (b,i,j,n)
__device__ float g_ao [(size_t)M_TOT*C];           // attention output, (m,c) row-major
__device__ float g_mean[B*NG];
__device__ float g_rstd[B*NG];

// ---------------- GroupNorm: stats ----------------
__global__ void gn_stats_kernel(const float* __restrict__ x) {
    int grp = blockIdx.x;                         // 0..255, groups are contiguous
    const float* p = x + (size_t)grp * GRP_ELEMS;
    float s = 0.f, s2 = 0.f;
    for (int i = threadIdx.x; i < GRP_ELEMS; i += blockDim.x) {
        float v = p[i]; s += v; s2 += v * v;
    }
    __shared__ float sh[512], sh2[512];
    sh[threadIdx.x] = s; sh2[threadIdx.x] = s2;
    __syncthreads();
    for (int off = blockDim.x >> 1; off > 0; off >>= 1) {
        if (threadIdx.x < off) {
            sh[threadIdx.x]  += sh[threadIdx.x + off];
            sh2[threadIdx.x] += sh2[threadIdx.x + off];
        }
        __syncthreads();
    }
    if (threadIdx.x == 0) {
        float mean = sh[0] * (1.0f / GRP_ELEMS);
        float var  = sh2[0] * (1.0f / GRP_ELEMS) - mean * mean;
        g_mean[grp] = mean;
        g_rstd[grp] = rsqrtf(var + EPS_GN);
    }
}

// ---------------- GroupNorm: apply ----------------
__global__ void gn_apply_kernel(const float4* __restrict__ x4,
                                const float* __restrict__ gamma,
                                const float* __restrict__ beta) {
    int i = blockIdx.x * blockDim.x + threadIdx.x;
    const int total4 = B*C*HW/4;
    if (i >= total4) return;
    int e   = i * 4;
    int cc  = (e / HW) % C;
    int grp = e / GRP_ELEMS;
    float m = g_mean[grp], r = g_rstd[grp];
    float ga = gamma[cc], be = beta[cc];
    float4 v = x4[i];
    v.x = (v.x - m) * r * ga + be;
    v.y = (v.y - m) * r * ga + be;
    v.z = (v.z - m) * r * ga + be;
    v.w = (v.w - m) * r * ga + be;
    ((float4*)g_xn)[i] = v;
}

// ---------------- SGEMM: Y[m,j] = sum_k A[m,k] * W[j,k] ----------------
// MODE 0: A is g_xn in (b, k, p) channel-major layout; Y row-major (m, j)
// MODE 1: A row-major (m, k); epilogue: out[b, j, p] = acc + bias[j] + resid[b,j,p]
#define BM 128
#define BN 64
#define BK 16
#define TM 8
#define TN 4

template<int MODE>
__global__ __launch_bounds__(256)
void gemm_kernel(const float* __restrict__ A, const float* __restrict__ W,
                 float* __restrict__ Y, const float* __restrict__ bias,
                 const float* __restrict__ resid) {
    __shared__ float As[BK][BM + 4];   // stride 132 floats (16B-multiple)
    __shared__ float Bs[BK][BN + 4];   // stride 68 floats

    const int tid = threadIdx.x;
    const int tx = tid & 15;           // 0..15
    const int ty = tid >> 4;           // 0..15
    const int m0 = blockIdx.y * BM;
    const int n0 = blockIdx.x * BN;
    const int bb = m0 / HW;            // BM divides HW, tiles never cross batch
    const int p0 = m0 % HW;

    float acc[TM][TN];
    #pragma unroll
    for (int r = 0; r < TM; r++)
        #pragma unroll
        for (int s = 0; s < TN; s++) acc[r][s] = 0.f;

    for (int k0 = 0; k0 < C; k0 += BK) {
        if (MODE == 0) {
            // channel-major A: A[m,k] = A[bb*C*HW + k*HW + p]
            int mm = tid & (BM - 1);          // 0..127
            int kk = tid >> 7;                // 0..1
            const float* ab = A + (size_t)bb * C * HW + p0 + mm;
            #pragma unroll
            for (int it = 0; it < 8; it++)
                As[kk + it*2][mm] = ab[(size_t)(k0 + kk + it*2) * HW];
        } else {
            // row-major A
            int kk = tid & (BK - 1);          // 0..15
            int mm = tid >> 4;                // 0..15
            #pragma unroll
            for (int it = 0; it < 8; it++)
                As[kk][mm + it*16] = A[(size_t)(m0 + mm + it*16) * C + k0 + kk];
        }
        {
            int kk = tid & (BK - 1);
            int jj = tid >> 4;                // 0..15
            #pragma unroll
            for (int it = 0; it < 4; it++)
                Bs[kk][jj + it*16] = W[(size_t)(n0 + jj + it*16) * C + k0 + kk];
        }
        __syncthreads();
        #pragma unroll
        for (int kk = 0; kk < BK; kk++) {
            float4 a0 = *(const float4*)&As[kk][ty * TM + 0];
            float4 a1 = *(const float4*)&As[kk][ty * TM + 4];
            float4 b0 = *(const float4*)&Bs[kk][tx * TN];
            float a[TM] = {a0.x, a0.y, a0.z, a0.w, a1.x, a1.y, a1.z, a1.w};
            float bvec[TN] = {b0.x, b0.y, b0.z, b0.w};
            #pragma unroll
            for (int r = 0; r < TM; r++)
                #pragma unroll
                for (int s = 0; s < TN; s++)
                    acc[r][s] += a[r] * bvec[s];
        }
        __syncthreads();
    }

    if (MODE == 0) {
        #pragma unroll
        for (int r = 0; r < TM; r++) {
            float4 v = make_float4(acc[r][0], acc[r][1], acc[r][2], acc[r][3]);
            *(float4*)&Y[(size_t)(m0 + ty*TM + r) * C + n0 + tx*TN] = v;
        }
    } else {
        // (b, j, p) layout + bias + residual
        #pragma unroll
        for (int s = 0; s < TN; s++) {
            int j = n0 + tx*TN + s;
            float bj = bias[j];
            size_t base = (size_t)bb * C * HW + (size_t)j * HW + p0 + ty*TM;
            float4 r0, r1;
            r0 = *(const float4*)&resid[base];
            r1 = *(const float4*)&resid[base + 4];
            float4 o0 = make_float4(acc[0][s] + bj + r0.x, acc[1][s] + bj + r0.y,
                                    acc[2][s] + bj + r0.z, acc[3][s] + bj + r0.w);
            float4 o1 = make_float4(acc[4][s] + bj + r1.x, acc[5][s] + bj + r1.y,
                                    acc[6][s] + bj + r1.z, acc[7][s] + bj + r1.w);
            *(float4*)&Y[base]     = o0;
            *(float4*)&Y[base + 4] = o1;
        }
    }
}

// ---------------- dots[b,i,j,n] = SCALE * dot(Q[b,n,i,:], K[b,n,j,:]) ----------------
__global__ void dots_kernel() {
    int n   = blockIdx.x * blockDim.x + threadIdx.x;   // 0..4095
    int bij = blockIdx.y;                              // 0..511
    int b = bij >> 6, ij = bij & 63;
    int i = ij >> 3, j = ij & 7;
    const float4* q = (const float4*)(g_q + ((size_t)b*HW + n) * C + i*HD);
    const float4* k = (const float4*)(g_k + ((size_t)b*HW + n) * C + j*HD);
    float acc = 0.f;
    #pragma unroll
    for (int d = 0; d < HD/4; d++) {
        float4 qa = q[d], kb = k[d];
        acc += qa.x*kb.x + qa.y*kb.y + qa.z*kb.z + qa.w*kb.w;
    }
    g_att[(size_t)bij * HW + n] = acc * SCALE_ATT;
}

// ---------------- softmax over n per (b,i,j) row, in place ----------------
__global__ void softmax_kernel() {
    float* row = g_att + (size_t)blockIdx.x * HW;
    __shared__ float sh[256];
    int tid = threadIdx.x;

    float mx = -1e30f;
    for (int n = tid; n < HW; n += 256) mx = fmaxf(mx, row[n]);
    sh[tid] = mx; __syncthreads();
    for (int off = 128; off > 0; off >>= 1) {
        if (tid < off) sh[tid] = fmaxf(sh[tid], sh[tid + off]);
        __syncthreads();
    }
    mx = sh[0]; __syncthreads();

    float sum = 0.f;
    for (int n = tid; n < HW; n += 256) sum += __expf(row[n] - mx);
    sh[tid] = sum; __syncthreads();
    for (int off = 128; off > 0; off >>= 1) {
        if (tid < off) sh[tid] += sh[tid + off];
        __syncthreads();
    }
    float inv = 1.f / sh[0];

    for (int n = tid; n < HW; n += 256) row[n] = __expf(row[n] - mx) * inv;
}

// ---------------- out[m, i*64+d] = sum_j att[b,i,j,n] * V[m, j*64+d] ----------------
__global__ void attv_kernel() {
    size_t idx = (size_t)blockIdx.x * 256 + threadIdx.x;  // < M_TOT*C
    int m  = (int)(idx >> 9);
    int cc = (int)(idx & 511);
    int b = m >> 12, n = m & 4095;
    int i = cc >> 6, d = cc & 63;
    const float* att = g_att + ((size_t)(b*64 + i*8)) * HW + n;
    const float* v   = g_v + (size_t)m * C + d;
    float acc = 0.f;
    #pragma unroll
    for (int j = 0; j < NHEAD; j++)
        acc += att[(size_t)j * HW] * v[j * HD];
    g_ao[idx] = acc;
}

// ---------------- launch ----------------
extern "C" void kernel_launch(void* const* d_in, const int* in_sizes, int n_in,
                              void* d_out, int out_size) {
    const float* x     = (const float*)d_in[0];
    const float* gamma = (const float*)d_in[1];
    const float* beta  = (const float*)d_in[2];
    const float* Wq    = (const float*)d_in[3];
    const float* Wk    = (const float*)d_in[4];
    const float* Wv    = (const float*)d_in[5];
    const float* Wp    = (const float*)d_in[6];
    const float* bp    = (const float*)d_in[7];
    float* out = (float*)d_out;

    float *p_xn, *p_q, *p_k, *p_v, *p_ao;
    cudaGetSymbolAddress((void**)&p_xn, g_xn);
    cudaGetSymbolAddress((void**)&p_q,  g_q);
    cudaGetSymbolAddress((void**)&p_k,  g_k);
    cudaGetSymbolAddress((void**)&p_v,  g_v);
    cudaGetSymbolAddress((void**)&p_ao, g_ao);

    gn_stats_kernel<<<B*NG, 512>>>(x);
    gn_apply_kernel<<<(B*C*HW/4 + 255)/256, 256>>>((const float4*)x, gamma, beta);

    dim3 gg(C/BN, M_TOT/BM);   // (8, 256)
    gemm_kernel<0><<<gg, 256>>>(p_xn, Wq, p_q, nullptr, nullptr);
    gemm_kernel<0><<<gg, 256>>>(p_xn, Wk, p_k, nullptr, nullptr);
    gemm_kernel<0><<<gg, 256>>>(p_xn, Wv, p_v, nullptr, nullptr);

    dots_kernel<<<dim3(HW/256, B*NHEAD*NHEAD), 256>>>();
    softmax_kernel<<<B*NHEAD*NHEAD, 256>>>();
    attv_kernel<<<(unsigned)((size_t)M_TOT*C/256), 256>>>();

    gemm_kernel<1><<<gg, 256>>>(p_ao, Wp, out, bp, p_xn);
}

// round 7
// speedup vs baseline: 2.0867x; 2.0867x over previous
#include <cuda_runtime.h>
#include <cuda_bf16.h>
#include <cstdint>
#include <cstddef>

#define B 8
#define C 512
#define HW 4096
#define M_TOT (B*HW)          // 32768
#define NG 32
#define CPG (C/NG)            // 16
#define GRP_ELEMS (CPG*HW)    // 65536
#define NHEAD 8
#define HD 64
#define EPS_GN 1e-6f
#define SCALE_ATT 8.0f        // sqrt(64), reference MULTIPLIES

// ---------------- scratch ----------------
__device__ float g_xn [B*C*HW];                 // normalized x, (b,c,p) fp32 (residual)
__device__ float g_q  [M_TOT*C];
__device__ float g_k  [M_TOT*C];
__device__ float g_v  [M_TOT*C];
__device__ float g_att[B*NHEAD*NHEAD*HW];       // dots then att, (b,i,j,n)
__device__ __nv_bfloat16 g_xa_hi[M_TOT*C];      // xn row-major (m,k) split
__device__ __nv_bfloat16 g_xa_lo[M_TOT*C];
__device__ __nv_bfloat16 g_w_hi[4*C*C];         // Wq,Wk,Wv,Wp splits (j,k)
__device__ __nv_bfloat16 g_w_lo[4*C*C];
__device__ __nv_bfloat16 g_ao_hi[M_TOT*C];      // attention out split (m,c)
__device__ __nv_bfloat16 g_ao_lo[M_TOT*C];
__device__ float g_mean[B*NG];
__device__ float g_rstd[B*NG];

// ---------------- helpers ----------------
__device__ __forceinline__ uint32_t smem_u32(const void* p) {
    uint32_t a;
    asm("{ .reg .u64 t; cvta.to.shared.u64 t, %1; cvt.u32.u64 %0, t; }" : "=r"(a) : "l"(p));
    return a;
}
#define CP_ASYNC16(s, g)  asm volatile("cp.async.cg.shared.global [%0], [%1], 16;" :: "r"(s), "l"(g))
#define CP_COMMIT()       asm volatile("cp.async.commit_group;" ::: "memory")
#define CP_WAIT(n)        asm volatile("cp.async.wait_group %0;" :: "n"(n) : "memory")

__device__ __forceinline__ void ldsm4(uint32_t* r, uint32_t addr) {
    asm volatile("ldmatrix.sync.aligned.m8n8.x4.shared.b16 {%0,%1,%2,%3}, [%4];"
        : "=r"(r[0]), "=r"(r[1]), "=r"(r[2]), "=r"(r[3]) : "r"(addr));
}
__device__ __forceinline__ void hmma(float* c, const uint32_t* a, const uint32_t* b) {
    asm volatile("mma.sync.aligned.m16n8k16.row.col.f32.bf16.bf16.f32 "
        "{%0,%1,%2,%3}, {%4,%5,%6,%7}, {%8,%9}, {%0,%1,%2,%3};"
        : "+f"(c[0]), "+f"(c[1]), "+f"(c[2]), "+f"(c[3])
        : "r"(a[0]), "r"(a[1]), "r"(a[2]), "r"(a[3]), "r"(b[0]), "r"(b[1]));
}

// ---------------- GroupNorm: stats ----------------
__global__ void gn_stats_kernel(const float* __restrict__ x) {
    int grp = blockIdx.x;
    const float* p = x + (size_t)grp * GRP_ELEMS;
    float s = 0.f, s2 = 0.f;
    for (int i = threadIdx.x; i < GRP_ELEMS; i += blockDim.x) {
        float v = p[i]; s += v; s2 += v * v;
    }
    __shared__ float sh[512], sh2[512];
    sh[threadIdx.x] = s; sh2[threadIdx.x] = s2;
    __syncthreads();
    for (int off = blockDim.x >> 1; off > 0; off >>= 1) {
        if (threadIdx.x < off) {
            sh[threadIdx.x]  += sh[threadIdx.x + off];
            sh2[threadIdx.x] += sh2[threadIdx.x + off];
        }
        __syncthreads();
    }
    if (threadIdx.x == 0) {
        float mean = sh[0] * (1.0f / GRP_ELEMS);
        float var  = sh2[0] * (1.0f / GRP_ELEMS) - mean * mean;
        g_mean[grp] = mean;
        g_rstd[grp] = rsqrtf(var + EPS_GN);
    }
}

// ---------------- GroupNorm: apply (fp32 xn, (b,c,p)) ----------------
__global__ void gn_apply_kernel(const float4* __restrict__ x4,
                                const float* __restrict__ gamma,
                                const float* __restrict__ beta) {
    int i = blockIdx.x * blockDim.x + threadIdx.x;
    const int total4 = B*C*HW/4;
    if (i >= total4) return;
    int e   = i * 4;
    int cc  = (e / HW) % C;
    int grp = e / GRP_ELEMS;
    float m = g_mean[grp], r = g_rstd[grp];
    float ga = gamma[cc], be = beta[cc];
    float4 v = x4[i];
    v.x = (v.x - m) * r * ga + be;
    v.y = (v.y - m) * r * ga + be;
    v.z = (v.z - m) * r * ga + be;
    v.w = (v.w - m) * r * ga + be;
    ((float4*)g_xn)[i] = v;
}

// ---------------- transpose+split: xn (b,c,p) -> (m,k) bf16 hi/lo ----------------
__global__ void split_xn_kernel() {
    __shared__ float sm[32][33];
    int p0 = blockIdx.x * 32, c0 = blockIdx.y * 32, b = blockIdx.z;
    int tx = threadIdx.x, ty = threadIdx.y;     // (32, 8)
    #pragma unroll
    for (int i = 0; i < 4; i++) {
        int c = c0 + ty + i*8;
        sm[ty + i*8][tx] = g_xn[(size_t)b*C*HW + (size_t)c*HW + p0 + tx];
    }
    __syncthreads();
    #pragma unroll
    for (int i = 0; i < 4; i++) {
        int p = p0 + ty + i*8;
        float v = sm[tx][ty + i*8];
        __nv_bfloat16 h = __float2bfloat16(v);
        size_t o = (size_t)(b*HW + p) * C + c0 + tx;
        g_xa_hi[o] = h;
        g_xa_lo[o] = __float2bfloat16(v - __bfloat162float(h));
    }
}

// ---------------- split weights ----------------
__global__ void split_w_kernel(const float* __restrict__ Wq, const float* __restrict__ Wk,
                               const float* __restrict__ Wv, const float* __restrict__ Wp) {
    int idx = blockIdx.x * 256 + threadIdx.x;   // < 4*C*C
    int wsel = idx >> 18;
    int off  = idx & (C*C - 1);
    const float* w = (wsel == 0) ? Wq : (wsel == 1) ? Wk : (wsel == 2) ? Wv : Wp;
    float v = w[off];
    __nv_bfloat16 h = __float2bfloat16(v);
    g_w_hi[idx] = h;
    g_w_lo[idx] = __float2bfloat16(v - __bfloat162float(h));
}

// ---------------- mma.sync bf16x3 GEMM: Y[m,j] = sum_k A[m,k]*W[j,k] ----------------
// MODE 0: Y fp32 row-major (m, C)
// MODE 1: Y (b,j,p) fp32 + bias[j] + resid[b,j,p]
#define GBM 128
#define GBN 64
#define GBK 32
#define NCH (C/GBK)          // 16
#define ASTR 80              // padded row stride (bytes): 32 bf16 + 16B pad
#define OFF_AL 10240         // 128*80
#define OFF_BH 20480
#define OFF_BL 25600         // + 64*80
#define STG 30720            // bytes per stage
#define SMEM_BYTES (2*STG)   // 61440

__device__ __forceinline__ void load_stage(uint32_t sb,
        const __nv_bfloat16* Ah, const __nv_bfloat16* Al,
        const __nv_bfloat16* Bh, const __nv_bfloat16* Bl,
        int m0, int n0, int k0, int tid) {
    #pragma unroll
    for (int i = 0; i < 2; i++) {
        int q = tid + i*256;
        int r = q >> 2, c = q & 3;
        uint32_t d = sb + r*ASTR + c*16;
        size_t g = (size_t)(m0 + r) * C + k0 + c*8;
        CP_ASYNC16(d, Ah + g);
        CP_ASYNC16(d + OFF_AL, Al + g);
    }
    {
        int r = tid >> 2, c = tid & 3;
        uint32_t d = sb + OFF_BH + r*ASTR + c*16;
        size_t g = (size_t)(n0 + r) * C + k0 + c*8;
        CP_ASYNC16(d, Bh + g);
        CP_ASYNC16(d + (OFF_BL - OFF_BH), Bl + g);
    }
}

template<int MODE>
__global__ __launch_bounds__(256, 2)
void tc_gemm(const __nv_bfloat16* __restrict__ Ah, const __nv_bfloat16* __restrict__ Al,
             const __nv_bfloat16* __restrict__ Bh, const __nv_bfloat16* __restrict__ Bl,
             float* __restrict__ Y, const float* __restrict__ bias,
             const float* __restrict__ resid) {
    extern __shared__ char smc[];
    const uint32_t smb = smem_u32(smc);
    const int tid = threadIdx.x;
    const int lane = tid & 31, wid = tid >> 5;
    const int wm = wid & 3, wn = wid >> 2;        // 4 (m) x 2 (n) warps
    const int n0 = blockIdx.x * GBN;
    const int m0 = blockIdx.y * GBM;
    const int bb = m0 / HW;
    const int p0 = m0 % HW;

    float acc[2][4][4];
    #pragma unroll
    for (int a = 0; a < 2; a++)
        #pragma unroll
        for (int b = 0; b < 4; b++)
            #pragma unroll
            for (int c = 0; c < 4; c++) acc[a][b][c] = 0.f;

    // ldmatrix lane-relative offsets
    const uint32_t aOff = (wm*32 + (lane & 15)) * ASTR + (lane >> 4) * 16;
    const uint32_t bOff = OFF_BH + (wn*32 + (lane & 7) + ((lane >> 4) & 1) * 8) * ASTR
                        + ((lane >> 3) & 1) * 16;

    load_stage(smb, Ah, Al, Bh, Bl, m0, n0, 0, tid);
    CP_COMMIT();

    for (int ch = 0; ch < NCH; ch++) {
        if (ch < NCH - 1) {
            load_stage(smb + ((ch + 1) & 1) * STG, Ah, Al, Bh, Bl, m0, n0, (ch + 1) * GBK, tid);
            CP_COMMIT();
            CP_WAIT(1);
        } else {
            CP_WAIT(0);
        }
        __syncthreads();
        const uint32_t sb = smb + (ch & 1) * STG;
        #pragma unroll
        for (int ks = 0; ks < 2; ks++) {
            uint32_t ah[2][4], al[2][4], bh[2][4], bl[2][4];
            #pragma unroll
            for (int mt = 0; mt < 2; mt++) {
                ldsm4(ah[mt], sb + aOff + mt * (16*ASTR) + ks * 32);
                ldsm4(al[mt], sb + OFF_AL + aOff + mt * (16*ASTR) + ks * 32);
            }
            #pragma unroll
            for (int np = 0; np < 2; np++) {
                ldsm4(bh[np], sb + bOff + np * (16*ASTR) + ks * 32);
                ldsm4(bl[np], sb + (OFF_BL - OFF_BH) + bOff + np * (16*ASTR) + ks * 32);
            }
            #pragma unroll
            for (int mt = 0; mt < 2; mt++)
                #pragma unroll
                for (int nt = 0; nt < 4; nt++) {
                    const uint32_t* bhp = &bh[nt >> 1][(nt & 1) * 2];
                    const uint32_t* blp = &bl[nt >> 1][(nt & 1) * 2];
                    hmma(acc[mt][nt], ah[mt], bhp);
                    hmma(acc[mt][nt], ah[mt], blp);
                    hmma(acc[mt][nt], al[mt], bhp);
                }
        }
        __syncthreads();
    }

    // ---------------- epilogue ----------------
    const int mrow = wm*32 + (lane >> 2);
    const int ncol = n0 + wn*32 + 2*(lane & 3);
    if (MODE == 0) {
        #pragma unroll
        for (int mt = 0; mt < 2; mt++)
            #pragma unroll
            for (int nt = 0; nt < 4; nt++) {
                int r = m0 + mrow + mt*16;
                int cq = ncol + nt*8;
                float2 v0 = make_float2(acc[mt][nt][0], acc[mt][nt][1]);
                float2 v1 = make_float2(acc[mt][nt][2], acc[mt][nt][3]);
                *(float2*)&Y[(size_t)r * C + cq]       = v0;
                *(float2*)&Y[(size_t)(r + 8) * C + cq] = v1;
            }
    } else {
        #pragma unroll
        for (int mt = 0; mt < 2; mt++)
            #pragma unroll
            for (int nt = 0; nt < 4; nt++) {
                int p = p0 + mrow + mt*16;
                int j = ncol + nt*8;
                float bj0 = bias[j], bj1 = bias[j + 1];
                size_t a00 = (size_t)bb*C*HW + (size_t)j*HW + p;
                Y[a00]          = acc[mt][nt][0] + bj0 + resid[a00];
                Y[a00 + HW]     = acc[mt][nt][1] + bj1 + resid[a00 + HW];
                Y[a00 + 8]      = acc[mt][nt][2] + bj0 + resid[a00 + 8];
                Y[a00 + HW + 8] = acc[mt][nt][3] + bj1 + resid[a00 + HW + 8];
            }
    }
}

// ---------------- dots: warp per (b,n); all 64 (i,j) pairs ----------------
__global__ void dots_kernel() {
    __shared__ float sQ[8][512];
    __shared__ float sK[8][512];
    int w = threadIdx.x >> 5, lane = threadIdx.x & 31;
    int m = blockIdx.x * 8 + w;                 // < 32768
    int b = m >> 12, n = m & 4095;
    const float4* q4 = (const float4*)(g_q + (size_t)m * C);
    const float4* k4 = (const float4*)(g_k + (size_t)m * C);
    #pragma unroll
    for (int i = 0; i < 4; i++) {
        ((float4*)sQ[w])[lane + i*32] = q4[lane + i*32];
        ((float4*)sK[w])[lane + i*32] = k4[lane + i*32];
    }
    __syncwarp();
    #pragma unroll
    for (int t = 0; t < 2; t++) {
        int p = lane + t*32;                    // 0..63
        int i = p >> 3, j = p & 7;
        const float* qi = &sQ[w][i * HD];
        const float* kj = &sK[w][j * HD];
        float acc = 0.f;
        #pragma unroll
        for (int d = 0; d < HD; d++) acc += qi[d] * kj[d];
        g_att[(size_t)(b*64 + p) * HW + n] = acc * SCALE_ATT;
    }
}

// ---------------- softmax over n per (b,i,j) row, in place ----------------
__global__ void softmax_kernel() {
    float* row = g_att + (size_t)blockIdx.x * HW;
    __shared__ float sh[256];
    int tid = threadIdx.x;

    float mx = -1e30f;
    for (int n = tid; n < HW; n += 256) mx = fmaxf(mx, row[n]);
    sh[tid] = mx; __syncthreads();
    for (int off = 128; off > 0; off >>= 1) {
        if (tid < off) sh[tid] = fmaxf(sh[tid], sh[tid + off]);
        __syncthreads();
    }
    mx = sh[0]; __syncthreads();

    float sum = 0.f;
    for (int n = tid; n < HW; n += 256) sum += __expf(row[n] - mx);
    sh[tid] = sum; __syncthreads();
    for (int off = 128; off > 0; off >>= 1) {
        if (tid < off) sh[tid] += sh[tid + off];
        __syncthreads();
    }
    float inv = 1.f / sh[0];

    for (int n = tid; n < HW; n += 256) row[n] = __expf(row[n] - mx) * inv;
}

// ---------------- attv: ao[m, i*64+d] = sum_j att[b,i,j,n] * V[m, j*64+d]; split bf16 ----------------
__global__ void attv_kernel() {
    size_t idx = (size_t)blockIdx.x * 256 + threadIdx.x;  // < M_TOT*C
    int m  = (int)(idx >> 9);
    int cc = (int)(idx & 511);
    int b = m >> 12, n = m & 4095;
    int i = cc >> 6, d = cc & 63;
    const float* att = g_att + ((size_t)(b*64 + i*8)) * HW + n;
    const float* v   = g_v + (size_t)m * C + d;
    float acc = 0.f;
    #pragma unroll
    for (int j = 0; j < NHEAD; j++)
        acc += att[(size_t)j * HW] * v[j * HD];
    __nv_bfloat16 h = __float2bfloat16(acc);
    g_ao_hi[idx] = h;
    g_ao_lo[idx] = __float2bfloat16(acc - __bfloat162float(h));
}

// ---------------- launch ----------------
extern "C" void kernel_launch(void* const* d_in, const int* in_sizes, int n_in,
                              void* d_out, int out_size) {
    const float* x     = (const float*)d_in[0];
    const float* gamma = (const float*)d_in[1];
    const float* beta  = (const float*)d_in[2];
    const float* Wq    = (const float*)d_in[3];
    const float* Wk    = (const float*)d_in[4];
    const float* Wv    = (const float*)d_in[5];
    const float* Wp    = (const float*)d_in[6];
    const float* bp    = (const float*)d_in[7];
    float* out = (float*)d_out;

    float *p_xn, *p_q, *p_k, *p_v;
    __nv_bfloat16 *p_xah, *p_xal, *p_wh, *p_wl, *p_aoh, *p_aol;
    cudaGetSymbolAddress((void**)&p_xn,  g_xn);
    cudaGetSymbolAddress((void**)&p_q,   g_q);
    cudaGetSymbolAddress((void**)&p_k,   g_k);
    cudaGetSymbolAddress((void**)&p_v,   g_v);
    cudaGetSymbolAddress((void**)&p_xah, g_xa_hi);
    cudaGetSymbolAddress((void**)&p_xal, g_xa_lo);
    cudaGetSymbolAddress((void**)&p_wh,  g_w_hi);
    cudaGetSymbolAddress((void**)&p_wl,  g_w_lo);
    cudaGetSymbolAddress((void**)&p_aoh, g_ao_hi);
    cudaGetSymbolAddress((void**)&p_aol, g_ao_lo);

    cudaFuncSetAttribute(tc_gemm<0>, cudaFuncAttributeMaxDynamicSharedMemorySize, SMEM_BYTES);
    cudaFuncSetAttribute(tc_gemm<1>, cudaFuncAttributeMaxDynamicSharedMemorySize, SMEM_BYTES);

    gn_stats_kernel<<<B*NG, 512>>>(x);
    gn_apply_kernel<<<(B*C*HW/4 + 255)/256, 256>>>((const float4*)x, gamma, beta);
    split_xn_kernel<<<dim3(HW/32, C/32, B), dim3(32, 8)>>>();
    split_w_kernel<<<4*C*C/256, 256>>>(Wq, Wk, Wv, Wp);

    dim3 gg(C/GBN, M_TOT/GBM);   // (8, 256)
    tc_gemm<0><<<gg, 256, SMEM_BYTES>>>(p_xah, p_xal, p_wh + 0*C*C, p_wl + 0*C*C, p_q, nullptr, nullptr);
    tc_gemm<0><<<gg, 256, SMEM_BYTES>>>(p_xah, p_xal, p_wh + 1*C*C, p_wl + 1*C*C, p_k, nullptr, nullptr);
    tc_gemm<0><<<gg, 256, SMEM_BYTES>>>(p_xah, p_xal, p_wh + 2*C*C, p_wl + 2*C*C, p_v, nullptr, nullptr);

    dots_kernel<<<M_TOT/8, 256>>>();
    softmax_kernel<<<B*NHEAD*NHEAD, 256>>>();
    attv_kernel<<<(unsigned)(M_TOT*(size_t)C/256), 256>>>();

    tc_gemm<1><<<gg, 256, SMEM_BYTES>>>(p_aoh, p_aol, p_wh + 3*C*C, p_wl + 3*C*C, out, bp, p_xn);
}